// round 13
// baseline (speedup 1.0000x reference)
#include <cuda_runtime.h>
#include <cuda_bf16.h>
#include <math.h>
#include <stdint.h>

// Problem constants
#define Bb 2
#define Nn 4096
#define Mm 32
#define Cc 256
#define Hh 8
#define T2 625
#define SCALE 0.17677669529663687f   // 32^-0.5
#define ROWS (Bb*Nn)                  // 8192

// attn smem: K tile 32x260 + q 256 + weights 256 + voffc 32
#define KP 260
#define ATTN_SMEM ((32*KP + 256 + 256 + 32) * 4) // 35456 bytes

// GEMM pipeline config
#define STAGES 4
#define APITCH 20
#define BPITCH 136
#define A_TILE (128*APITCH)
#define B_TILE (16*BPITCH)
#define STAGE_FLOATS (A_TILE + B_TILE)
#define GEMM_SMEM (STAGES*STAGE_FLOATS*4) // 75776 bytes

// Scratch
__device__ float g_qkv[(size_t)ROWS * 768];      // [q(256) | per-head (k32,v32) x8]
__device__ float g_attnout[(size_t)ROWS * Cc];   // tf32-rounded attention output
__device__ float g_feat_t[(size_t)ROWS * Cc];    // tf32-rounded feat
__device__ float g_wt[256 * 768];                // [k][ Wq(256) | Wkv(512) ] rounded
__device__ float g_wtp[256 * 256];               // Wproj rounded
__device__ float g_bias768[768];                 // [bq | bkv]
__device__ float g_pe[T2 * Hh];
__device__ int   g_mask_is_u8;

// ---------------------------------------------------------------------------
__device__ __forceinline__ uint32_t f2tf32(float f)
{
    uint32_t r;
    asm("cvt.rna.tf32.f32 %0, %1;" : "=r"(r) : "f"(f));
    return r;
}
__device__ __forceinline__ float rna_tf32(float f)
{
    return __uint_as_float(f2tf32(f));
}

__global__ void detect_mask_kernel(const unsigned int* __restrict__ m)
{
    int found = 0;
#pragma unroll
    for (int j = 0; j < 8; j++) {
        if (m[threadIdx.x + j * 256] > 1u) found = 1;
    }
    int any = __syncthreads_or(found);
    if (threadIdx.x == 0) g_mask_is_u8 = any;
}

__global__ void pe_kernel(const float* __restrict__ pre_table,
                          const float* __restrict__ W_pe,
                          const float* __restrict__ b_pe)
{
    int i = blockIdx.x * blockDim.x + threadIdx.x;
    if (i >= T2 * Hh) return;
    int t = i >> 3;
    int h = i & 7;
    float acc = b_pe[h];
#pragma unroll
    for (int j = 0; j < 5; j++)
        acc += pre_table[t * 5 + j] * W_pe[j * Hh + h];
    g_pe[i] = acc;
}

// prep: rna-round feat (524288 float4s)
__global__ void conv_feat_kernel(const float* __restrict__ f)
{
    int i = blockIdx.x * blockDim.x + threadIdx.x;
    float4 v = ((const float4*)f)[i];
    v.x = rna_tf32(v.x); v.y = rna_tf32(v.y);
    v.z = rna_tf32(v.z); v.w = rna_tf32(v.w);
    ((float4*)g_feat_t)[i] = v;
}

// prep: round weights (layout preserved, Wq|Wkv fused), combine biases.
// idx: [0,65536) Wq, [65536,196608) Wkv, [196608,262144) Wproj, [262144,262912) bias
__global__ void prep_w_kernel(
    const float* __restrict__ Wq, const float* __restrict__ Wkv,
    const float* __restrict__ Wproj,
    const float* __restrict__ bq, const float* __restrict__ bkv)
{
    int idx = blockIdx.x * blockDim.x + threadIdx.x;
    if (idx < 65536) {
        int k = idx >> 8, n = idx & 255;
        g_wt[k * 768 + n] = rna_tf32(Wq[idx]);
    } else if (idx < 196608) {
        int j = idx - 65536;
        int k = j >> 9, n = j & 511;
        g_wt[k * 768 + 256 + n] = rna_tf32(Wkv[j]);
    } else if (idx < 262144) {
        int j = idx - 196608;
        g_wtp[j] = rna_tf32(Wproj[j]);
    } else if (idx < 262912) {
        int j = idx - 262144;
        g_bias768[j] = (j < 256) ? bq[j] : bkv[j - 256];
    }
}

// ---------------------------------------------------------------------------
__device__ __forceinline__ void mma_tf32(float* d, const uint32_t* a, const uint32_t* b)
{
    asm volatile(
        "mma.sync.aligned.m16n8k8.row.col.f32.tf32.tf32.f32 "
        "{%0,%1,%2,%3}, {%4,%5,%6,%7}, {%8,%9}, {%0,%1,%2,%3};"
        : "+f"(d[0]), "+f"(d[1]), "+f"(d[2]), "+f"(d[3])
        : "r"(a[0]), "r"(a[1]), "r"(a[2]), "r"(a[3]), "r"(b[0]), "r"(b[1]));
}

__device__ __forceinline__ uint32_t smem_u32(const void* p)
{
    uint32_t r;
    asm("{ .reg .u64 t; cvta.to.shared.u64 t, %1; cvt.u32.u64 %0, t; }"
        : "=r"(r) : "l"(p));
    return r;
}

__device__ __forceinline__ void cp16(uint32_t dst, const void* src)
{
    asm volatile("cp.async.ca.shared.global [%0], [%1], 16;"
                 :: "r"(dst), "l"(src));
}

// ---------------------------------------------------------------------------
// tf32 GEMM body (BM=BN=128, BK=16, 4-stage cp.async). Inputs pre-rounded
// to tf32 values -> fragments feed mma.sync raw (no cvt in the inner loop).
// ---------------------------------------------------------------------------
__device__ __forceinline__ void gemm_body(
    const float* __restrict__ A, const float* __restrict__ W,
    const float* __restrict__ bias, float* __restrict__ Cout,
    int K, int Ncols, int ldout, int block_m, int wcol, int outcol,
    float* sm)
{
    const int tid = threadIdx.x;
    const int wid = tid >> 5;
    const int lane = tid & 31;
    const int wm = (wid & 3) * 32;
    const int wn = (wid >> 2) * 64;
    const int lr = lane >> 2;
    const int lc = lane & 3;

    const int arow = tid >> 1;
    const int acol = (tid & 1) * 8;
    const int brow = tid >> 4;
    const int bcol = (tid & 15) * 8;

    const float* Aptr = A + (size_t)(block_m + arow) * K + acol;
    const float* Wptr = W + (size_t)brow * Ncols + wcol + bcol;

    float acc[2][8][4];
#pragma unroll
    for (int i = 0; i < 2; i++)
#pragma unroll
        for (int j = 0; j < 8; j++)
#pragma unroll
            for (int t = 0; t < 4; t++) acc[i][j][t] = 0.f;

    const int NIT = K >> 4;

    auto issue_tile = [&](int s, int k0) {
        float* as = sm + s * STAGE_FLOATS;
        float* bs = as + A_TILE;
        uint32_t ad = smem_u32(as + arow * APITCH + acol);
        const char* asrc = (const char*)(Aptr + k0);
        cp16(ad, asrc);
        cp16(ad + 16, asrc + 16);
        uint32_t bd = smem_u32(bs + brow * BPITCH + bcol);
        const char* bsrc = (const char*)(Wptr + (size_t)k0 * Ncols);
        cp16(bd, bsrc);
        cp16(bd + 16, bsrc + 16);
    };

#pragma unroll
    for (int s = 0; s < STAGES - 1; s++) {
        if (s < NIT) issue_tile(s, s * 16);
        asm volatile("cp.async.commit_group;");
    }

    for (int it = 0; it < NIT; it++) {
        asm volatile("cp.async.wait_group %0;" :: "n"(STAGES - 2));
        __syncthreads();
        if (it + STAGES - 1 < NIT)
            issue_tile((it + STAGES - 1) % STAGES, (it + STAGES - 1) * 16);
        asm volatile("cp.async.commit_group;");

        const uint32_t* as = (const uint32_t*)(sm + (it % STAGES) * STAGE_FLOATS);
        const uint32_t* bs = as + A_TILE;
#pragma unroll
        for (int kk = 0; kk < 16; kk += 8) {
            uint32_t afr[2][4], bfr[8][2];
#pragma unroll
            for (int mf = 0; mf < 2; mf++) {
                const int r = wm + mf * 16 + lr;
                afr[mf][0] = as[r * APITCH + kk + lc];
                afr[mf][1] = as[(r + 8) * APITCH + kk + lc];
                afr[mf][2] = as[r * APITCH + kk + lc + 4];
                afr[mf][3] = as[(r + 8) * APITCH + kk + lc + 4];
            }
#pragma unroll
            for (int nf = 0; nf < 8; nf++) {
                const int cn = wn + nf * 8 + lr;
                bfr[nf][0] = bs[(kk + lc) * BPITCH + cn];
                bfr[nf][1] = bs[(kk + lc + 4) * BPITCH + cn];
            }
#pragma unroll
            for (int mf = 0; mf < 2; mf++)
#pragma unroll
                for (int nf = 0; nf < 8; nf++)
                    mma_tf32(acc[mf][nf], afr[mf], bfr[nf]);
        }
    }

#pragma unroll
    for (int mf = 0; mf < 2; mf++) {
        const int row0 = block_m + wm + mf * 16 + lr;
#pragma unroll
        for (int nf = 0; nf < 8; nf++) {
            const int cl = wn + nf * 8 + lc * 2;
            float2 bv = *(const float2*)(bias + wcol + cl);
            float2 v0 = make_float2(acc[mf][nf][0] + bv.x, acc[mf][nf][1] + bv.y);
            float2 v1 = make_float2(acc[mf][nf][2] + bv.x, acc[mf][nf][3] + bv.y);
            *(float2*)(Cout + (size_t)row0 * ldout + outcol + cl) = v0;
            *(float2*)(Cout + (size_t)(row0 + 8) * ldout + outcol + cl) = v1;
        }
    }
}

// Fused Q+KV projection over the combined [k][768] weight: grid (6, 64).
__global__ __launch_bounds__(256, 2) void qkv_gemm_kernel(float* __restrict__ qkv)
{
    extern __shared__ float sm[];
    gemm_body(g_feat_t, g_wt, g_bias768, qkv, 256, 768, 768,
              blockIdx.y * 128, blockIdx.x * 128, blockIdx.x * 128, sm);
}

// Output projection: grid (2, 64).
__global__ __launch_bounds__(256, 2) void proj_gemm_kernel(
    const float* __restrict__ bias, float* __restrict__ out)
{
    extern __shared__ float sm[];
    gemm_body(g_attnout, g_wtp, bias, out, 256, 256, 256,
              blockIdx.y * 128, blockIdx.x * 128, blockIdx.x * 128, sm);
}

// ---------------------------------------------------------------------------
// Fused gather + scores + softmax + weighted-V with active-member compaction.
// ---------------------------------------------------------------------------
__device__ __forceinline__ bool read_mask(const void* cm, int idx, int is_u8)
{
    if (is_u8) return ((const unsigned char*)cm)[idx] != 0;
    return ((const int*)cm)[idx] != 0;
}

__global__ __launch_bounds__(256) void attn_kernel(
    const int* __restrict__ member_idx,
    const void* __restrict__ cluster_mask,
    const int* __restrict__ pe_idx,
    const float* __restrict__ blank_k,
    const float* __restrict__ blank_v)
{
    extern __shared__ float smem[];
    float* kv    = smem;                 // 32 x KP (K only)
    float* qsh   = smem + 32 * KP;       // 256
    float* aw    = qsh + 256;            // 8 heads x 32 compacted weights
    int*   voffc = (int*)(aw + 256);     // 32 compacted V-row offsets

    const int bn   = blockIdx.x;
    const int tid  = threadIdx.x;
    const int h    = tid >> 5;
    const int lane = tid & 31;
    const int b    = bn >> 12;     // N = 4096
    const int is_u8 = g_mask_is_u8;

    // ---- phase 1: stage q + gathered K (cp.async), mask-predicated ----
    const int mbase = bn * Mm;
    const int mrow = tid >> 3;
    const int sub  = tid & 7;
    const bool msk_stage = read_mask(cluster_mask, mbase + mrow, is_u8);

    if (msk_stage) {
        const int gidx = __ldg(member_idx + mbase + mrow);
        const char* src = (const char*)(g_qkv + ((size_t)(b * Nn + gidx)) * 768 + 256);
        uint32_t dst_base = smem_u32(kv + mrow * KP);
#pragma unroll
        for (int j = 0; j < 8; j++) {
            cp16(dst_base + j * 128 + sub * 16, src + j * 256 + sub * 16);
        }
    }
    asm volatile("cp.async.commit_group;");

    qsh[tid] = g_qkv[(size_t)bn * 768 + tid];

    const bool msk = read_mask(cluster_mask, mbase + lane, is_u8);
    const unsigned wmask = __ballot_sync(0xFFFFFFFFu, msk);
    const int n_act = __popc(wmask);
    const int n4 = (n_act + 3) & ~3;
    const int pos = __popc(wmask & ((1u << lane) - 1u));

    if (tid < 32) {
        if (msk) {
            const int gidx_l = __ldg(member_idx + mbase + lane);
            voffc[pos] = gidx_l * 768;
        }
        if (lane >= n_act && lane < n4) voffc[lane] = 0;
    }

    asm volatile("cp.async.wait_group 0;");
    __syncthreads();

    // ---- phase 2: score + softmax (lane = member m) ----
    const float* qh = qsh + h * 32;
    float score = -3.0e38f;
    if (msk) {
        const float4* krow4 = (const float4*)(kv + lane * KP + h * 32);
        float sc = 0.f;
#pragma unroll
        for (int i = 0; i < 8; i++) {
            float4 kk = krow4[i];
            sc = fmaf(kk.x, qh[4*i+0], sc);
            sc = fmaf(kk.y, qh[4*i+1], sc);
            sc = fmaf(kk.z, qh[4*i+2], sc);
            sc = fmaf(kk.w, qh[4*i+3], sc);
        }
        const int pid = pe_idx[mbase + lane];
        score = sc * SCALE + g_pe[pid * Hh + h];
    }

    float bsp = qh[lane] * blank_k[h * 32 + lane];
#pragma unroll
    for (int o = 16; o > 0; o >>= 1)
        bsp += __shfl_xor_sync(0xFFFFFFFFu, bsp, o);
    const float bs = bsp * SCALE;

    float mx = score;
#pragma unroll
    for (int o = 16; o > 0; o >>= 1)
        mx = fmaxf(mx, __shfl_xor_sync(0xFFFFFFFFu, mx, o));
    mx = fmaxf(mx, bs);

    float p  = __expf(score - mx);
    float pb = __expf(bs - mx);
    float s = p;
#pragma unroll
    for (int o = 16; o > 0; o >>= 1)
        s += __shfl_xor_sync(0xFFFFFFFFu, s, o);
    s += pb;
    const float inv = 1.f / s;
    const float a  = p * inv;
    const float ab = pb * inv;

    if (msk) aw[h * 32 + pos] = a;
    if (lane >= n_act && lane < n4) aw[h * 32 + lane] = 0.f;
    __syncwarp();

    // ---- phase 3: dense weighted V sum over active members ----
    const float* vb = g_qkv + (size_t)b * Nn * 768 + 256 + h * 64 + 32 + lane;
    float out = ab * blank_v[h * 32 + lane];
    float out2 = 0.f;
    for (int c = 0; c < n4; c += 4) {
        int4   ro = *(const int4*)(voffc + c);
        float4 wv = *(const float4*)(aw + h * 32 + c);
        float v0 = __ldg(vb + ro.x);
        float v1 = __ldg(vb + ro.y);
        float v2 = __ldg(vb + ro.z);
        float v3 = __ldg(vb + ro.w);
        out  = fmaf(wv.x, v0, out);
        out2 = fmaf(wv.y, v1, out2);
        out  = fmaf(wv.z, v2, out);
        out2 = fmaf(wv.w, v3, out2);
    }
    out += out2;

    // tf32-rounded store: proj GEMM consumes this raw
    g_attnout[(size_t)bn * Cc + h * 32 + lane] = rna_tf32(out);
}

// ---------------------------------------------------------------------------
extern "C" void kernel_launch(void* const* d_in, const int* in_sizes, int n_in,
                              void* d_out, int out_size)
{
    const float* feat   = (const float*)d_in[0];
    const int*   member = (const int*)d_in[1];
    const void*  mask   = d_in[2];
    const int*   peidx  = (const int*)d_in[3];

    int p = 4;
    for (int i = 4; i < n_in; i++) {
        if (in_sizes[i] == 3125) { p = i; break; }
    }
    const float* pre_table = (const float*)d_in[p];
    const float* Wq        = (const float*)d_in[p + 1];
    const float* bq        = (const float*)d_in[p + 2];
    const float* Wkv       = (const float*)d_in[p + 3];
    const float* bkv       = (const float*)d_in[p + 4];
    const float* W_pe      = (const float*)d_in[p + 5];
    const float* b_pe      = (const float*)d_in[p + 6];
    const float* blank_k   = (const float*)d_in[p + 7];
    const float* blank_v   = (const float*)d_in[p + 8];
    const float* Wproj     = (const float*)d_in[p + 9];
    const float* bproj     = (const float*)d_in[p + 10];
    float* out = (float*)d_out;

    float* qkv = nullptr;
    cudaGetSymbolAddress((void**)&qkv, g_qkv);

    cudaFuncSetAttribute(attn_kernel,
                         cudaFuncAttributeMaxDynamicSharedMemorySize, ATTN_SMEM);
    cudaFuncSetAttribute(qkv_gemm_kernel,
                         cudaFuncAttributeMaxDynamicSharedMemorySize, GEMM_SMEM);
    cudaFuncSetAttribute(proj_gemm_kernel,
                         cudaFuncAttributeMaxDynamicSharedMemorySize, GEMM_SMEM);

    detect_mask_kernel<<<1, 256>>>((const unsigned int*)mask);
    pe_kernel<<<(T2 * Hh + 255) / 256, 256>>>(pre_table, W_pe, b_pe);
    conv_feat_kernel<<<2048, 256>>>(feat);
    prep_w_kernel<<<1028, 256>>>(Wq, Wkv, Wproj, bq, bkv);

    {   // fused Q+KV projection
        dim3 grid(6, ROWS / 128);
        qkv_gemm_kernel<<<grid, 256, GEMM_SMEM>>>(qkv);
    }

    attn_kernel<<<ROWS, 256, ATTN_SMEM>>>(member, mask, peidx, blank_k, blank_v);

    {   // output projection
        dim3 grid(2, ROWS / 128);
        proj_gemm_kernel<<<grid, 256, GEMM_SMEM>>>(bproj, out);
    }
}

// round 14
// speedup vs baseline: 1.0395x; 1.0395x over previous
#include <cuda_runtime.h>
#include <cuda_bf16.h>
#include <math.h>
#include <stdint.h>

// Problem constants
#define Bb 2
#define Nn 4096
#define Mm 32
#define Cc 256
#define Hh 8
#define T2 625
#define SCALE 0.17677669529663687f   // 32^-0.5
#define ROWS (Bb*Nn)                  // 8192

// attn smem: K tile 32x260 + q 256 + weights 256 + voffc 32
#define KP 260
#define ATTN_SMEM ((32*KP + 256 + 256 + 32) * 4) // 35456 bytes

// GEMM pipeline config
#define STAGES 4
#define APITCH 20
#define BPITCH 136
#define A_TILE (128*APITCH)
#define B_TILE (16*BPITCH)
#define STAGE_FLOATS (A_TILE + B_TILE)
#define GEMM_SMEM (STAGES*STAGE_FLOATS*4) // 75776 bytes

// Scratch
__device__ float g_qkv[(size_t)ROWS * 768];      // [q(256) | per-head (k32,v32) x8]
__device__ float g_attnout[(size_t)ROWS * Cc];   // tf32-rounded attention output
__device__ float g_wt[256 * 768];                // [k][ Wq(256) | Wkv(512) ] rounded
__device__ float g_wtp[256 * 256];               // Wproj rounded
__device__ float g_bias768[768];                 // [bq | bkv]
__device__ float g_pe[T2 * Hh];
__device__ int   g_mask_is_u8;

// ---------------------------------------------------------------------------
__device__ __forceinline__ uint32_t f2tf32(float f)
{
    uint32_t r;
    asm("cvt.rna.tf32.f32 %0, %1;" : "=r"(r) : "f"(f));
    return r;
}
__device__ __forceinline__ float rna_tf32(float f)
{
    return __uint_as_float(f2tf32(f));
}

__global__ void detect_mask_kernel(const unsigned int* __restrict__ m)
{
    int found = 0;
#pragma unroll
    for (int j = 0; j < 8; j++) {
        if (m[threadIdx.x + j * 256] > 1u) found = 1;
    }
    int any = __syncthreads_or(found);
    if (threadIdx.x == 0) g_mask_is_u8 = any;
}

__global__ void pe_kernel(const float* __restrict__ pre_table,
                          const float* __restrict__ W_pe,
                          const float* __restrict__ b_pe)
{
    int i = blockIdx.x * blockDim.x + threadIdx.x;
    if (i >= T2 * Hh) return;
    int t = i >> 3;
    int h = i & 7;
    float acc = b_pe[h];
#pragma unroll
    for (int j = 0; j < 5; j++)
        acc += pre_table[t * 5 + j] * W_pe[j * Hh + h];
    g_pe[i] = acc;
}

// prep: round weights into fused layout, float4-vectorized.
// float4 idx: [0,16384) Wq -> g_wt[k*768 + n], [16384,49152) Wkv -> g_wt[k*768+256+n],
// [49152,65536) Wproj -> g_wtp, [65536,65728) bias (768 floats).
__global__ void prep_w_kernel(
    const float* __restrict__ Wq, const float* __restrict__ Wkv,
    const float* __restrict__ Wproj,
    const float* __restrict__ bq, const float* __restrict__ bkv)
{
    int idx = blockIdx.x * blockDim.x + threadIdx.x;
    if (idx < 16384) {
        float4 v = ((const float4*)Wq)[idx];
        v.x = rna_tf32(v.x); v.y = rna_tf32(v.y);
        v.z = rna_tf32(v.z); v.w = rna_tf32(v.w);
        int k = idx >> 6, n4 = idx & 63;          // 64 float4 per 256-wide row
        ((float4*)g_wt)[k * 192 + n4] = v;        // 768/4 = 192
    } else if (idx < 49152) {
        int j = idx - 16384;
        float4 v = ((const float4*)Wkv)[j];
        v.x = rna_tf32(v.x); v.y = rna_tf32(v.y);
        v.z = rna_tf32(v.z); v.w = rna_tf32(v.w);
        int k = j >> 7, n4 = j & 127;             // 128 float4 per 512-wide row
        ((float4*)g_wt)[k * 192 + 64 + n4] = v;
    } else if (idx < 65536) {
        int j = idx - 49152;
        float4 v = ((const float4*)Wproj)[j];
        v.x = rna_tf32(v.x); v.y = rna_tf32(v.y);
        v.z = rna_tf32(v.z); v.w = rna_tf32(v.w);
        ((float4*)g_wtp)[j] = v;
    } else if (idx < 65728) {
        int j = idx - 65536;                      // float index group
        int base = j * 4;
#pragma unroll
        for (int t = 0; t < 4; t++) {
            int e = base + t;
            g_bias768[e] = (e < 256) ? bq[e] : bkv[e - 256];
        }
    }
}

// ---------------------------------------------------------------------------
__device__ __forceinline__ void mma_tf32(float* d, const uint32_t* a, const uint32_t* b)
{
    asm volatile(
        "mma.sync.aligned.m16n8k8.row.col.f32.tf32.tf32.f32 "
        "{%0,%1,%2,%3}, {%4,%5,%6,%7}, {%8,%9}, {%0,%1,%2,%3};"
        : "+f"(d[0]), "+f"(d[1]), "+f"(d[2]), "+f"(d[3])
        : "r"(a[0]), "r"(a[1]), "r"(a[2]), "r"(a[3]), "r"(b[0]), "r"(b[1]));
}

__device__ __forceinline__ uint32_t smem_u32(const void* p)
{
    uint32_t r;
    asm("{ .reg .u64 t; cvta.to.shared.u64 t, %1; cvt.u32.u64 %0, t; }"
        : "=r"(r) : "l"(p));
    return r;
}

__device__ __forceinline__ void cp16(uint32_t dst, const void* src)
{
    asm volatile("cp.async.ca.shared.global [%0], [%1], 16;"
                 :: "r"(dst), "l"(src));
}

// ---------------------------------------------------------------------------
// tf32 GEMM body (BM=BN=128, BK=16, 4-stage cp.async pipeline).
// W is pre-rounded; A fragments are cvt'd in-loop iff CVT_A.
// ---------------------------------------------------------------------------
template <bool CVT_A>
__device__ __forceinline__ void gemm_body(
    const float* __restrict__ A, const float* __restrict__ W,
    const float* __restrict__ bias, float* __restrict__ Cout,
    int K, int Ncols, int ldout, int block_m, int wcol, int outcol,
    float* sm)
{
    const int tid = threadIdx.x;
    const int wid = tid >> 5;
    const int lane = tid & 31;
    const int wm = (wid & 3) * 32;
    const int wn = (wid >> 2) * 64;
    const int lr = lane >> 2;
    const int lc = lane & 3;

    const int arow = tid >> 1;
    const int acol = (tid & 1) * 8;
    const int brow = tid >> 4;
    const int bcol = (tid & 15) * 8;

    const float* Aptr = A + (size_t)(block_m + arow) * K + acol;
    const float* Wptr = W + (size_t)brow * Ncols + wcol + bcol;

    float acc[2][8][4];
#pragma unroll
    for (int i = 0; i < 2; i++)
#pragma unroll
        for (int j = 0; j < 8; j++)
#pragma unroll
            for (int t = 0; t < 4; t++) acc[i][j][t] = 0.f;

    const int NIT = K >> 4;

    auto issue_tile = [&](int s, int k0) {
        float* as = sm + s * STAGE_FLOATS;
        float* bs = as + A_TILE;
        uint32_t ad = smem_u32(as + arow * APITCH + acol);
        const char* asrc = (const char*)(Aptr + k0);
        cp16(ad, asrc);
        cp16(ad + 16, asrc + 16);
        uint32_t bd = smem_u32(bs + brow * BPITCH + bcol);
        const char* bsrc = (const char*)(Wptr + (size_t)k0 * Ncols);
        cp16(bd, bsrc);
        cp16(bd + 16, bsrc + 16);
    };

#pragma unroll
    for (int s = 0; s < STAGES - 1; s++) {
        if (s < NIT) issue_tile(s, s * 16);
        asm volatile("cp.async.commit_group;");
    }

    for (int it = 0; it < NIT; it++) {
        asm volatile("cp.async.wait_group %0;" :: "n"(STAGES - 2));
        __syncthreads();
        if (it + STAGES - 1 < NIT)
            issue_tile((it + STAGES - 1) % STAGES, (it + STAGES - 1) * 16);
        asm volatile("cp.async.commit_group;");

        const float*    asf = sm + (it % STAGES) * STAGE_FLOATS;
        const uint32_t* asu = (const uint32_t*)asf;
        const uint32_t* bs  = asu + A_TILE;
#pragma unroll
        for (int kk = 0; kk < 16; kk += 8) {
            uint32_t afr[2][4], bfr[8][2];
#pragma unroll
            for (int mf = 0; mf < 2; mf++) {
                const int r = wm + mf * 16 + lr;
                if (CVT_A) {
                    afr[mf][0] = f2tf32(asf[r * APITCH + kk + lc]);
                    afr[mf][1] = f2tf32(asf[(r + 8) * APITCH + kk + lc]);
                    afr[mf][2] = f2tf32(asf[r * APITCH + kk + lc + 4]);
                    afr[mf][3] = f2tf32(asf[(r + 8) * APITCH + kk + lc + 4]);
                } else {
                    afr[mf][0] = asu[r * APITCH + kk + lc];
                    afr[mf][1] = asu[(r + 8) * APITCH + kk + lc];
                    afr[mf][2] = asu[r * APITCH + kk + lc + 4];
                    afr[mf][3] = asu[(r + 8) * APITCH + kk + lc + 4];
                }
            }
#pragma unroll
            for (int nf = 0; nf < 8; nf++) {
                const int cn = wn + nf * 8 + lr;
                bfr[nf][0] = bs[(kk + lc) * BPITCH + cn];
                bfr[nf][1] = bs[(kk + lc + 4) * BPITCH + cn];
            }
#pragma unroll
            for (int mf = 0; mf < 2; mf++)
#pragma unroll
                for (int nf = 0; nf < 8; nf++)
                    mma_tf32(acc[mf][nf], afr[mf], bfr[nf]);
        }
    }

#pragma unroll
    for (int mf = 0; mf < 2; mf++) {
        const int row0 = block_m + wm + mf * 16 + lr;
#pragma unroll
        for (int nf = 0; nf < 8; nf++) {
            const int cl = wn + nf * 8 + lc * 2;
            float2 bv = *(const float2*)(bias + wcol + cl);
            float2 v0 = make_float2(acc[mf][nf][0] + bv.x, acc[mf][nf][1] + bv.y);
            float2 v1 = make_float2(acc[mf][nf][2] + bv.x, acc[mf][nf][3] + bv.y);
            *(float2*)(Cout + (size_t)row0 * ldout + outcol + cl) = v0;
            *(float2*)(Cout + (size_t)(row0 + 8) * ldout + outcol + cl) = v1;
        }
    }
}

// Fused Q+KV projection over combined [k][768] weights: grid (6, 64).
__global__ __launch_bounds__(256, 2) void qkv_gemm_kernel(
    const float* __restrict__ feat, float* __restrict__ qkv)
{
    extern __shared__ float sm[];
    gemm_body<true>(feat, g_wt, g_bias768, qkv, 256, 768, 768,
                    blockIdx.y * 128, blockIdx.x * 128, blockIdx.x * 128, sm);
}

// Output projection: grid (2, 64). A pre-rounded -> no cvt.
__global__ __launch_bounds__(256, 2) void proj_gemm_kernel(
    const float* __restrict__ bias, float* __restrict__ out)
{
    extern __shared__ float sm[];
    gemm_body<false>(g_attnout, g_wtp, bias, out, 256, 256, 256,
                     blockIdx.y * 128, blockIdx.x * 128, blockIdx.x * 128, sm);
}

// ---------------------------------------------------------------------------
// Fused gather + scores + softmax + weighted-V with active-member compaction.
// ---------------------------------------------------------------------------
__device__ __forceinline__ bool read_mask(const void* cm, int idx, int is_u8)
{
    if (is_u8) return ((const unsigned char*)cm)[idx] != 0;
    return ((const int*)cm)[idx] != 0;
}

__global__ __launch_bounds__(256) void attn_kernel(
    const int* __restrict__ member_idx,
    const void* __restrict__ cluster_mask,
    const int* __restrict__ pe_idx,
    const float* __restrict__ blank_k,
    const float* __restrict__ blank_v)
{
    extern __shared__ float smem[];
    float* kv    = smem;                 // 32 x KP (K only)
    float* qsh   = smem + 32 * KP;       // 256
    float* aw    = qsh + 256;            // 8 heads x 32 compacted weights
    int*   voffc = (int*)(aw + 256);     // 32 compacted V-row offsets

    const int bn   = blockIdx.x;
    const int tid  = threadIdx.x;
    const int h    = tid >> 5;
    const int lane = tid & 31;
    const int b    = bn >> 12;     // N = 4096
    const int is_u8 = g_mask_is_u8;

    // ---- phase 1: stage q + gathered K (cp.async), mask-predicated ----
    const int mbase = bn * Mm;
    const int mrow = tid >> 3;
    const int sub  = tid & 7;
    const bool msk_stage = read_mask(cluster_mask, mbase + mrow, is_u8);

    if (msk_stage) {
        const int gidx = __ldg(member_idx + mbase + mrow);
        const char* src = (const char*)(g_qkv + ((size_t)(b * Nn + gidx)) * 768 + 256);
        uint32_t dst_base = smem_u32(kv + mrow * KP);
#pragma unroll
        for (int j = 0; j < 8; j++) {
            cp16(dst_base + j * 128 + sub * 16, src + j * 256 + sub * 16);
        }
    }
    asm volatile("cp.async.commit_group;");

    qsh[tid] = g_qkv[(size_t)bn * 768 + tid];

    const bool msk = read_mask(cluster_mask, mbase + lane, is_u8);
    const unsigned wmask = __ballot_sync(0xFFFFFFFFu, msk);
    const int n_act = __popc(wmask);
    const int n4 = (n_act + 3) & ~3;
    const int pos = __popc(wmask & ((1u << lane) - 1u));

    if (tid < 32) {
        if (msk) {
            const int gidx_l = __ldg(member_idx + mbase + lane);
            voffc[pos] = gidx_l * 768;
        }
        if (lane >= n_act && lane < n4) voffc[lane] = 0;
    }

    asm volatile("cp.async.wait_group 0;");
    __syncthreads();

    // ---- phase 2: score + softmax (lane = member m) ----
    const float* qh = qsh + h * 32;
    float score = -3.0e38f;
    if (msk) {
        const float4* krow4 = (const float4*)(kv + lane * KP + h * 32);
        float sc = 0.f;
#pragma unroll
        for (int i = 0; i < 8; i++) {
            float4 kk = krow4[i];
            sc = fmaf(kk.x, qh[4*i+0], sc);
            sc = fmaf(kk.y, qh[4*i+1], sc);
            sc = fmaf(kk.z, qh[4*i+2], sc);
            sc = fmaf(kk.w, qh[4*i+3], sc);
        }
        const int pid = pe_idx[mbase + lane];
        score = sc * SCALE + g_pe[pid * Hh + h];
    }

    float bsp = qh[lane] * blank_k[h * 32 + lane];
#pragma unroll
    for (int o = 16; o > 0; o >>= 1)
        bsp += __shfl_xor_sync(0xFFFFFFFFu, bsp, o);
    const float bs = bsp * SCALE;

    float mx = score;
#pragma unroll
    for (int o = 16; o > 0; o >>= 1)
        mx = fmaxf(mx, __shfl_xor_sync(0xFFFFFFFFu, mx, o));
    mx = fmaxf(mx, bs);

    float p  = __expf(score - mx);
    float pb = __expf(bs - mx);
    float s = p;
#pragma unroll
    for (int o = 16; o > 0; o >>= 1)
        s += __shfl_xor_sync(0xFFFFFFFFu, s, o);
    s += pb;
    const float inv = 1.f / s;
    const float a  = p * inv;
    const float ab = pb * inv;

    if (msk) aw[h * 32 + pos] = a;
    if (lane >= n_act && lane < n4) aw[h * 32 + lane] = 0.f;
    __syncwarp();

    // ---- phase 3: dense weighted V sum over active members ----
    const float* vb = g_qkv + (size_t)b * Nn * 768 + 256 + h * 64 + 32 + lane;
    float out = ab * blank_v[h * 32 + lane];
    float out2 = 0.f;
    for (int c = 0; c < n4; c += 4) {
        int4   ro = *(const int4*)(voffc + c);
        float4 wv = *(const float4*)(aw + h * 32 + c);
        float v0 = __ldg(vb + ro.x);
        float v1 = __ldg(vb + ro.y);
        float v2 = __ldg(vb + ro.z);
        float v3 = __ldg(vb + ro.w);
        out  = fmaf(wv.x, v0, out);
        out2 = fmaf(wv.y, v1, out2);
        out  = fmaf(wv.z, v2, out);
        out2 = fmaf(wv.w, v3, out2);
    }
    out += out2;

    // tf32-rounded store: proj GEMM consumes this raw
    g_attnout[(size_t)bn * Cc + h * 32 + lane] = rna_tf32(out);
}

// ---------------------------------------------------------------------------
extern "C" void kernel_launch(void* const* d_in, const int* in_sizes, int n_in,
                              void* d_out, int out_size)
{
    const float* feat   = (const float*)d_in[0];
    const int*   member = (const int*)d_in[1];
    const void*  mask   = d_in[2];
    const int*   peidx  = (const int*)d_in[3];

    int p = 4;
    for (int i = 4; i < n_in; i++) {
        if (in_sizes[i] == 3125) { p = i; break; }
    }
    const float* pre_table = (const float*)d_in[p];
    const float* Wq        = (const float*)d_in[p + 1];
    const float* bq        = (const float*)d_in[p + 2];
    const float* Wkv       = (const float*)d_in[p + 3];
    const float* bkv       = (const float*)d_in[p + 4];
    const float* W_pe      = (const float*)d_in[p + 5];
    const float* b_pe      = (const float*)d_in[p + 6];
    const float* blank_k   = (const float*)d_in[p + 7];
    const float* blank_v   = (const float*)d_in[p + 8];
    const float* Wproj     = (const float*)d_in[p + 9];
    const float* bproj     = (const float*)d_in[p + 10];
    float* out = (float*)d_out;

    float* qkv = nullptr;
    cudaGetSymbolAddress((void**)&qkv, g_qkv);

    cudaFuncSetAttribute(attn_kernel,
                         cudaFuncAttributeMaxDynamicSharedMemorySize, ATTN_SMEM);
    cudaFuncSetAttribute(qkv_gemm_kernel,
                         cudaFuncAttributeMaxDynamicSharedMemorySize, GEMM_SMEM);
    cudaFuncSetAttribute(proj_gemm_kernel,
                         cudaFuncAttributeMaxDynamicSharedMemorySize, GEMM_SMEM);

    detect_mask_kernel<<<1, 256>>>((const unsigned int*)mask);
    pe_kernel<<<(T2 * Hh + 255) / 256, 256>>>(pre_table, W_pe, b_pe);
    prep_w_kernel<<<257, 256>>>(Wq, Wkv, Wproj, bq, bkv);

    {   // fused Q+KV projection
        dim3 grid(6, ROWS / 128);
        qkv_gemm_kernel<<<grid, 256, GEMM_SMEM>>>(feat, qkv);
    }

    attn_kernel<<<ROWS, 256, ATTN_SMEM>>>(member, mask, peidx, blank_k, blank_v);

    {   // output projection
        dim3 grid(2, ROWS / 128);
        proj_gemm_kernel<<<grid, 256, GEMM_SMEM>>>(bproj, out);
    }
}

// round 15
// speedup vs baseline: 1.0603x; 1.0200x over previous
#include <cuda_runtime.h>
#include <cuda_bf16.h>
#include <math.h>
#include <stdint.h>

// Problem constants
#define Bb 2
#define Nn 4096
#define Mm 32
#define Cc 256
#define Hh 8
#define T2 625
#define SCALE 0.17677669529663687f   // 32^-0.5
#define ROWS (Bb*Nn)                  // 8192

// attn smem: K tile 32x260 + q 256 + weights 256 + voffc 32
#define KP 260
#define ATTN_SMEM ((32*KP + 256 + 256 + 32) * 4) // 35456 bytes

// GEMM pipeline config
#define STAGES 4
#define APITCH 20
#define BPITCH 136
#define A_TILE (128*APITCH)
#define B_TILE (16*BPITCH)
#define STAGE_FLOATS (A_TILE + B_TILE)
#define GEMM_SMEM (STAGES*STAGE_FLOATS*4) // 75776 bytes

// Scratch
__device__ float g_qkv[(size_t)ROWS * 768];      // [q(256) | per-head (k32,v32) x8]
__device__ float g_attnout[(size_t)ROWS * Cc];   // tf32-rounded attention output
__device__ float g_wt[256 * 768];                // [k][ Wq(256) | Wkv(512) ] rounded
__device__ float g_wtp[256 * 256];               // Wproj rounded
__device__ float g_bias768[768];                 // [bq | bkv]
__device__ float g_pe[T2 * Hh];
__device__ int   g_mask_is_u8;

// ---------------------------------------------------------------------------
__device__ __forceinline__ uint32_t f2tf32(float f)
{
    uint32_t r;
    asm("cvt.rna.tf32.f32 %0, %1;" : "=r"(r) : "f"(f));
    return r;
}
__device__ __forceinline__ float rna_tf32(float f)
{
    return __uint_as_float(f2tf32(f));
}

__global__ void detect_mask_kernel(const unsigned int* __restrict__ m)
{
    int found = 0;
#pragma unroll
    for (int j = 0; j < 8; j++) {
        if (m[threadIdx.x + j * 256] > 1u) found = 1;
    }
    int any = __syncthreads_or(found);
    if (threadIdx.x == 0) g_mask_is_u8 = any;
}

__global__ void pe_kernel(const float* __restrict__ pre_table,
                          const float* __restrict__ W_pe,
                          const float* __restrict__ b_pe)
{
    int i = blockIdx.x * blockDim.x + threadIdx.x;
    if (i >= T2 * Hh) return;
    int t = i >> 3;
    int h = i & 7;
    float acc = b_pe[h];
#pragma unroll
    for (int j = 0; j < 5; j++)
        acc += pre_table[t * 5 + j] * W_pe[j * Hh + h];
    g_pe[i] = acc;
}

// prep: round weights into fused layout, float4-vectorized.
__global__ void prep_w_kernel(
    const float* __restrict__ Wq, const float* __restrict__ Wkv,
    const float* __restrict__ Wproj,
    const float* __restrict__ bq, const float* __restrict__ bkv)
{
    int idx = blockIdx.x * blockDim.x + threadIdx.x;
    if (idx < 16384) {
        float4 v = ((const float4*)Wq)[idx];
        v.x = rna_tf32(v.x); v.y = rna_tf32(v.y);
        v.z = rna_tf32(v.z); v.w = rna_tf32(v.w);
        int k = idx >> 6, n4 = idx & 63;
        ((float4*)g_wt)[k * 192 + n4] = v;
    } else if (idx < 49152) {
        int j = idx - 16384;
        float4 v = ((const float4*)Wkv)[j];
        v.x = rna_tf32(v.x); v.y = rna_tf32(v.y);
        v.z = rna_tf32(v.z); v.w = rna_tf32(v.w);
        int k = j >> 7, n4 = j & 127;
        ((float4*)g_wt)[k * 192 + 64 + n4] = v;
    } else if (idx < 65536) {
        int j = idx - 49152;
        float4 v = ((const float4*)Wproj)[j];
        v.x = rna_tf32(v.x); v.y = rna_tf32(v.y);
        v.z = rna_tf32(v.z); v.w = rna_tf32(v.w);
        ((float4*)g_wtp)[j] = v;
    } else if (idx < 65728) {
        int j = idx - 65536;
        int base = j * 4;
#pragma unroll
        for (int t = 0; t < 4; t++) {
            int e = base + t;
            g_bias768[e] = (e < 256) ? bq[e] : bkv[e - 256];
        }
    }
}

// ---------------------------------------------------------------------------
__device__ __forceinline__ void mma_tf32(float* d, const uint32_t* a, const uint32_t* b)
{
    asm volatile(
        "mma.sync.aligned.m16n8k8.row.col.f32.tf32.tf32.f32 "
        "{%0,%1,%2,%3}, {%4,%5,%6,%7}, {%8,%9}, {%0,%1,%2,%3};"
        : "+f"(d[0]), "+f"(d[1]), "+f"(d[2]), "+f"(d[3])
        : "r"(a[0]), "r"(a[1]), "r"(a[2]), "r"(a[3]), "r"(b[0]), "r"(b[1]));
}

__device__ __forceinline__ uint32_t smem_u32(const void* p)
{
    uint32_t r;
    asm("{ .reg .u64 t; cvta.to.shared.u64 t, %1; cvt.u32.u64 %0, t; }"
        : "=r"(r) : "l"(p));
    return r;
}

__device__ __forceinline__ void cp16(uint32_t dst, const void* src)
{
    asm volatile("cp.async.ca.shared.global [%0], [%1], 16;"
                 :: "r"(dst), "l"(src));
}

// ---------------------------------------------------------------------------
// tf32 GEMM body, 512 threads (16 warps), BM=BN=128, BK=16, 4-stage cp.async.
// Warp tile 32x32 = 2x4 m16n8k8 frags -> ~32 acc regs/thread, 2 CTAs/SM.
// W pre-rounded; A fragments cvt'd in-loop iff CVT_A.
// ---------------------------------------------------------------------------
template <bool CVT_A>
__device__ __forceinline__ void gemm_body512(
    const float* __restrict__ A, const float* __restrict__ W,
    const float* __restrict__ bias, float* __restrict__ Cout,
    int K, int Ncols, int ldout, int block_m, int wcol, int outcol,
    float* sm)
{
    const int tid = threadIdx.x;
    const int wid = tid >> 5;          // 0..15
    const int lane = tid & 31;
    const int wm = (wid & 3) * 32;     // warp m offset
    const int wn = (wid >> 2) * 32;    // warp n offset
    const int lr = lane >> 2;          // 0..7
    const int lc = lane & 3;           // 0..3

    // staging: each thread 1 A cp16 + 1 B cp16
    const int arow = tid >> 2;          // 0..127
    const int acol = (tid & 3) * 4;     // 0,4,8,12
    const int brow = wid;               // 0..15
    const int bcol = lane * 4;          // 0..124

    const float* Aptr = A + (size_t)(block_m + arow) * K + acol;
    const float* Wptr = W + (size_t)brow * Ncols + wcol + bcol;

    float acc[2][4][4];
#pragma unroll
    for (int i = 0; i < 2; i++)
#pragma unroll
        for (int j = 0; j < 4; j++)
#pragma unroll
            for (int t = 0; t < 4; t++) acc[i][j][t] = 0.f;

    const int NIT = K >> 4;

    auto issue_tile = [&](int s, int k0) {
        float* as = sm + s * STAGE_FLOATS;
        float* bs = as + A_TILE;
        cp16(smem_u32(as + arow * APITCH + acol), Aptr + k0);
        cp16(smem_u32(bs + brow * BPITCH + bcol), Wptr + (size_t)k0 * Ncols);
    };

#pragma unroll
    for (int s = 0; s < STAGES - 1; s++) {
        if (s < NIT) issue_tile(s, s * 16);
        asm volatile("cp.async.commit_group;");
    }

    for (int it = 0; it < NIT; it++) {
        asm volatile("cp.async.wait_group %0;" :: "n"(STAGES - 2));
        __syncthreads();
        if (it + STAGES - 1 < NIT)
            issue_tile((it + STAGES - 1) % STAGES, (it + STAGES - 1) * 16);
        asm volatile("cp.async.commit_group;");

        const float*    asf = sm + (it % STAGES) * STAGE_FLOATS;
        const uint32_t* asu = (const uint32_t*)asf;
        const uint32_t* bs  = asu + A_TILE;
#pragma unroll
        for (int kk = 0; kk < 16; kk += 8) {
            uint32_t afr[2][4], bfr[4][2];
#pragma unroll
            for (int mf = 0; mf < 2; mf++) {
                const int r = wm + mf * 16 + lr;
                if (CVT_A) {
                    afr[mf][0] = f2tf32(asf[r * APITCH + kk + lc]);
                    afr[mf][1] = f2tf32(asf[(r + 8) * APITCH + kk + lc]);
                    afr[mf][2] = f2tf32(asf[r * APITCH + kk + lc + 4]);
                    afr[mf][3] = f2tf32(asf[(r + 8) * APITCH + kk + lc + 4]);
                } else {
                    afr[mf][0] = asu[r * APITCH + kk + lc];
                    afr[mf][1] = asu[(r + 8) * APITCH + kk + lc];
                    afr[mf][2] = asu[r * APITCH + kk + lc + 4];
                    afr[mf][3] = asu[(r + 8) * APITCH + kk + lc + 4];
                }
            }
#pragma unroll
            for (int nf = 0; nf < 4; nf++) {
                const int cn = wn + nf * 8 + lr;
                bfr[nf][0] = bs[(kk + lc) * BPITCH + cn];
                bfr[nf][1] = bs[(kk + lc + 4) * BPITCH + cn];
            }
#pragma unroll
            for (int mf = 0; mf < 2; mf++)
#pragma unroll
                for (int nf = 0; nf < 4; nf++)
                    mma_tf32(acc[mf][nf], afr[mf], bfr[nf]);
        }
    }

#pragma unroll
    for (int mf = 0; mf < 2; mf++) {
        const int row0 = block_m + wm + mf * 16 + lr;
#pragma unroll
        for (int nf = 0; nf < 4; nf++) {
            const int cl = wn + nf * 8 + lc * 2;
            float2 bv = *(const float2*)(bias + wcol + cl);
            float2 v0 = make_float2(acc[mf][nf][0] + bv.x, acc[mf][nf][1] + bv.y);
            float2 v1 = make_float2(acc[mf][nf][2] + bv.x, acc[mf][nf][3] + bv.y);
            *(float2*)(Cout + (size_t)row0 * ldout + outcol + cl) = v0;
            *(float2*)(Cout + (size_t)(row0 + 8) * ldout + outcol + cl) = v1;
        }
    }
}

// Fused Q+KV projection over combined [k][768] weights: grid (6, 64).
__global__ __launch_bounds__(512, 2) void qkv_gemm_kernel(
    const float* __restrict__ feat, float* __restrict__ qkv)
{
    extern __shared__ float sm[];
    gemm_body512<true>(feat, g_wt, g_bias768, qkv, 256, 768, 768,
                       blockIdx.y * 128, blockIdx.x * 128, blockIdx.x * 128, sm);
}

// Output projection: grid (2, 64). A pre-rounded -> no cvt.
__global__ __launch_bounds__(512, 2) void proj_gemm_kernel(
    const float* __restrict__ bias, float* __restrict__ out)
{
    extern __shared__ float sm[];
    gemm_body512<false>(g_attnout, g_wtp, bias, out, 256, 256, 256,
                        blockIdx.y * 128, blockIdx.x * 128, blockIdx.x * 128, sm);
}

// ---------------------------------------------------------------------------
// Fused gather + scores + softmax + weighted-V with active-member compaction.
// ---------------------------------------------------------------------------
__device__ __forceinline__ bool read_mask(const void* cm, int idx, int is_u8)
{
    if (is_u8) return ((const unsigned char*)cm)[idx] != 0;
    return ((const int*)cm)[idx] != 0;
}

__global__ __launch_bounds__(256) void attn_kernel(
    const int* __restrict__ member_idx,
    const void* __restrict__ cluster_mask,
    const int* __restrict__ pe_idx,
    const float* __restrict__ blank_k,
    const float* __restrict__ blank_v)
{
    extern __shared__ float smem[];
    float* kv    = smem;                 // 32 x KP (K only)
    float* qsh   = smem + 32 * KP;       // 256
    float* aw    = qsh + 256;            // 8 heads x 32 compacted weights
    int*   voffc = (int*)(aw + 256);     // 32 compacted V-row offsets

    const int bn   = blockIdx.x;
    const int tid  = threadIdx.x;
    const int h    = tid >> 5;
    const int lane = tid & 31;
    const int b    = bn >> 12;     // N = 4096
    const int is_u8 = g_mask_is_u8;

    // ---- phase 1: stage q + gathered K (cp.async), mask-predicated ----
    const int mbase = bn * Mm;
    const int mrow = tid >> 3;
    const int sub  = tid & 7;
    const bool msk_stage = read_mask(cluster_mask, mbase + mrow, is_u8);

    if (msk_stage) {
        const int gidx = __ldg(member_idx + mbase + mrow);
        const char* src = (const char*)(g_qkv + ((size_t)(b * Nn + gidx)) * 768 + 256);
        uint32_t dst_base = smem_u32(kv + mrow * KP);
#pragma unroll
        for (int j = 0; j < 8; j++) {
            cp16(dst_base + j * 128 + sub * 16, src + j * 256 + sub * 16);
        }
    }
    asm volatile("cp.async.commit_group;");

    qsh[tid] = g_qkv[(size_t)bn * 768 + tid];

    const bool msk = read_mask(cluster_mask, mbase + lane, is_u8);
    const unsigned wmask = __ballot_sync(0xFFFFFFFFu, msk);
    const int n_act = __popc(wmask);
    const int n4 = (n_act + 3) & ~3;
    const int pos = __popc(wmask & ((1u << lane) - 1u));

    if (tid < 32) {
        if (msk) {
            const int gidx_l = __ldg(member_idx + mbase + lane);
            voffc[pos] = gidx_l * 768;
        }
        if (lane >= n_act && lane < n4) voffc[lane] = 0;
    }

    asm volatile("cp.async.wait_group 0;");
    __syncthreads();

    // ---- phase 2: score + softmax (lane = member m) ----
    const float* qh = qsh + h * 32;
    float score = -3.0e38f;
    if (msk) {
        const float4* krow4 = (const float4*)(kv + lane * KP + h * 32);
        float sc = 0.f;
#pragma unroll
        for (int i = 0; i < 8; i++) {
            float4 kk = krow4[i];
            sc = fmaf(kk.x, qh[4*i+0], sc);
            sc = fmaf(kk.y, qh[4*i+1], sc);
            sc = fmaf(kk.z, qh[4*i+2], sc);
            sc = fmaf(kk.w, qh[4*i+3], sc);
        }
        const int pid = pe_idx[mbase + lane];
        score = sc * SCALE + g_pe[pid * Hh + h];
    }

    float bsp = qh[lane] * blank_k[h * 32 + lane];
#pragma unroll
    for (int o = 16; o > 0; o >>= 1)
        bsp += __shfl_xor_sync(0xFFFFFFFFu, bsp, o);
    const float bs = bsp * SCALE;

    float mx = score;
#pragma unroll
    for (int o = 16; o > 0; o >>= 1)
        mx = fmaxf(mx, __shfl_xor_sync(0xFFFFFFFFu, mx, o));
    mx = fmaxf(mx, bs);

    float p  = __expf(score - mx);
    float pb = __expf(bs - mx);
    float s = p;
#pragma unroll
    for (int o = 16; o > 0; o >>= 1)
        s += __shfl_xor_sync(0xFFFFFFFFu, s, o);
    s += pb;
    const float inv = 1.f / s;
    const float a  = p * inv;
    const float ab = pb * inv;

    if (msk) aw[h * 32 + pos] = a;
    if (lane >= n_act && lane < n4) aw[h * 32 + lane] = 0.f;
    __syncwarp();

    // ---- phase 3: dense weighted V sum over active members ----
    const float* vb = g_qkv + (size_t)b * Nn * 768 + 256 + h * 64 + 32 + lane;
    float out = ab * blank_v[h * 32 + lane];
    float out2 = 0.f;
    for (int c = 0; c < n4; c += 4) {
        int4   ro = *(const int4*)(voffc + c);
        float4 wv = *(const float4*)(aw + h * 32 + c);
        float v0 = __ldg(vb + ro.x);
        float v1 = __ldg(vb + ro.y);
        float v2 = __ldg(vb + ro.z);
        float v3 = __ldg(vb + ro.w);
        out  = fmaf(wv.x, v0, out);
        out2 = fmaf(wv.y, v1, out2);
        out  = fmaf(wv.z, v2, out);
        out2 = fmaf(wv.w, v3, out2);
    }
    out += out2;

    // tf32-rounded store: proj GEMM consumes this raw
    g_attnout[(size_t)bn * Cc + h * 32 + lane] = rna_tf32(out);
}

// ---------------------------------------------------------------------------
extern "C" void kernel_launch(void* const* d_in, const int* in_sizes, int n_in,
                              void* d_out, int out_size)
{
    const float* feat   = (const float*)d_in[0];
    const int*   member = (const int*)d_in[1];
    const void*  mask   = d_in[2];
    const int*   peidx  = (const int*)d_in[3];

    int p = 4;
    for (int i = 4; i < n_in; i++) {
        if (in_sizes[i] == 3125) { p = i; break; }
    }
    const float* pre_table = (const float*)d_in[p];
    const float* Wq        = (const float*)d_in[p + 1];
    const float* bq        = (const float*)d_in[p + 2];
    const float* Wkv       = (const float*)d_in[p + 3];
    const float* bkv       = (const float*)d_in[p + 4];
    const float* W_pe      = (const float*)d_in[p + 5];
    const float* b_pe      = (const float*)d_in[p + 6];
    const float* blank_k   = (const float*)d_in[p + 7];
    const float* blank_v   = (const float*)d_in[p + 8];
    const float* Wproj     = (const float*)d_in[p + 9];
    const float* bproj     = (const float*)d_in[p + 10];
    float* out = (float*)d_out;

    float* qkv = nullptr;
    cudaGetSymbolAddress((void**)&qkv, g_qkv);

    cudaFuncSetAttribute(attn_kernel,
                         cudaFuncAttributeMaxDynamicSharedMemorySize, ATTN_SMEM);
    cudaFuncSetAttribute(qkv_gemm_kernel,
                         cudaFuncAttributeMaxDynamicSharedMemorySize, GEMM_SMEM);
    cudaFuncSetAttribute(proj_gemm_kernel,
                         cudaFuncAttributeMaxDynamicSharedMemorySize, GEMM_SMEM);

    detect_mask_kernel<<<1, 256>>>((const unsigned int*)mask);
    pe_kernel<<<(T2 * Hh + 255) / 256, 256>>>(pre_table, W_pe, b_pe);
    prep_w_kernel<<<257, 256>>>(Wq, Wkv, Wproj, bq, bkv);

    {   // fused Q+KV projection
        dim3 grid(6, ROWS / 128);
        qkv_gemm_kernel<<<grid, 512, GEMM_SMEM>>>(feat, qkv);
    }

    attn_kernel<<<ROWS, 256, ATTN_SMEM>>>(member, mask, peidx, blank_k, blank_v);

    {   // output projection
        dim3 grid(2, ROWS / 128);
        proj_gemm_kernel<<<grid, 512, GEMM_SMEM>>>(bproj, out);
    }
}

// round 16
// speedup vs baseline: 1.0606x; 1.0003x over previous
#include <cuda_runtime.h>
#include <cuda_bf16.h>
#include <math.h>
#include <stdint.h>

// Problem constants
#define Bb 2
#define Nn 4096
#define Mm 32
#define Cc 256
#define Hh 8
#define T2 625
#define SCALE 0.17677669529663687f   // 32^-0.5
#define ROWS (Bb*Nn)                  // 8192

// attn smem
#define KP 260
#define ATTN_SMEM ((32*KP + 256 + 256 + 32) * 4) // 35456 bytes

// GEMM pipeline config (BM=BN=128, BK=16, pitch 20 both operands)
#define STAGES 4
#define APITCH 20
#define BPITCH 20
#define A_TILE (128*APITCH)               // 2560 floats
#define B_TILE (128*BPITCH)               // 2560 floats
#define STAGE_FLOATS (A_TILE + B_TILE)    // 5120
#define GEMM_SMEM (STAGES*STAGE_FLOATS*4) // 81920 bytes

// Scratch
__device__ float g_qkv[(size_t)ROWS * 768];      // [q(256) | per-head (k32,v32) x8]
__device__ float g_attnout[(size_t)ROWS * Cc];   // tf32-rounded attention output
__device__ float g_wt[768 * 256];                // [n][k]: rows = Wq n | Wkv n (rounded)
__device__ float g_wtp[256 * 256];               // [n][k] Wproj (rounded)
__device__ float g_bias768[768];                 // [bq | bkv]
__device__ float g_pe[T2 * Hh];
__device__ int   g_mask_is_u8;

// ---------------------------------------------------------------------------
__device__ __forceinline__ uint32_t f2tf32(float f)
{
    uint32_t r;
    asm("cvt.rna.tf32.f32 %0, %1;" : "=r"(r) : "f"(f));
    return r;
}
__device__ __forceinline__ float rna_tf32(float f)
{
    return __uint_as_float(f2tf32(f));
}

__global__ void detect_mask_kernel(const unsigned int* __restrict__ m)
{
    int found = 0;
#pragma unroll
    for (int j = 0; j < 8; j++) {
        if (m[threadIdx.x + j * 256] > 1u) found = 1;
    }
    int any = __syncthreads_or(found);
    if (threadIdx.x == 0) g_mask_is_u8 = any;
}

__global__ void pe_kernel(const float* __restrict__ pre_table,
                          const float* __restrict__ W_pe,
                          const float* __restrict__ b_pe)
{
    int i = blockIdx.x * blockDim.x + threadIdx.x;
    if (i >= T2 * Hh) return;
    int t = i >> 3;
    int h = i & 7;
    float acc = b_pe[h];
#pragma unroll
    for (int j = 0; j < 5; j++)
        acc += pre_table[t * 5 + j] * W_pe[j * Hh + h];
    g_pe[i] = acc;
}

// ---------------------------------------------------------------------------
// prep: tiled transpose+round of weights into [n][k] layout; bias merge.
// 257 blocks of (32,8). Blocks 0-63 Wq, 64-191 Wkv, 192-255 Wproj, 256 bias.
// ---------------------------------------------------------------------------
__global__ void prep_w_kernel(
    const float* __restrict__ Wq, const float* __restrict__ Wkv,
    const float* __restrict__ Wproj,
    const float* __restrict__ bq, const float* __restrict__ bkv)
{
    __shared__ float t[32][33];
    const int b = blockIdx.x;
    const int tx = threadIdx.x, ty = threadIdx.y;

    if (b == 256) {
        int tid = ty * 32 + tx;
#pragma unroll
        for (int j = 0; j < 3; j++) {
            int e = tid + j * 256;
            g_bias768[e] = (e < 256) ? bq[e] : bkv[e - 256];
        }
        return;
    }

    const float* src; float* dst;
    int N, kt, nt, row_off;
    if (b < 64)      { src = Wq;    N = 256; kt = b >> 3;        nt = b & 7;         dst = g_wt;  row_off = 0; }
    else if (b < 192){ int j = b - 64;  src = Wkv;  N = 512; kt = j >> 4; nt = j & 15; dst = g_wt;  row_off = 256; }
    else             { int j = b - 192; src = Wproj;N = 256; kt = j >> 3; nt = j & 7;  dst = g_wtp; row_off = 0; }

#pragma unroll
    for (int j = 0; j < 4; j++) {
        int k = kt * 32 + ty + j * 8;
        t[ty + j * 8][tx] = rna_tf32(src[(size_t)k * N + nt * 32 + tx]);
    }
    __syncthreads();
#pragma unroll
    for (int j = 0; j < 4; j++) {
        int n = nt * 32 + ty + j * 8;
        dst[(size_t)(row_off + n) * 256 + kt * 32 + tx] = t[tx][ty + j * 8];
    }
}

// ---------------------------------------------------------------------------
__device__ __forceinline__ void mma_tf32(float* d, const uint32_t* a,
                                         uint32_t b0, uint32_t b1)
{
    asm volatile(
        "mma.sync.aligned.m16n8k8.row.col.f32.tf32.tf32.f32 "
        "{%0,%1,%2,%3}, {%4,%5,%6,%7}, {%8,%9}, {%0,%1,%2,%3};"
        : "+f"(d[0]), "+f"(d[1]), "+f"(d[2]), "+f"(d[3])
        : "r"(a[0]), "r"(a[1]), "r"(a[2]), "r"(a[3]), "r"(b0), "r"(b1));
}

__device__ __forceinline__ uint32_t smem_u32(const void* p)
{
    uint32_t r;
    asm("{ .reg .u64 t; cvta.to.shared.u64 t, %1; cvt.u32.u64 %0, t; }"
        : "=r"(r) : "l"(p));
    return r;
}

__device__ __forceinline__ void cp16(uint32_t dst, const void* src)
{
    asm volatile("cp.async.ca.shared.global [%0], [%1], 16;"
                 :: "r"(dst), "l"(src));
}

#define LDSM4(r, addr) \
    asm volatile("ldmatrix.sync.aligned.m8n8.x4.shared.b16 {%0,%1,%2,%3}, [%4];" \
        : "=r"((r)[0]), "=r"((r)[1]), "=r"((r)[2]), "=r"((r)[3]) : "r"(addr))

// ---------------------------------------------------------------------------
// tf32 GEMM body, 512 threads, BM=BN=128, BK=16, 4-stage cp.async,
// ldmatrix fragment loads. A [m][k] row-major, WT [n][k] row-major (K=256).
// W pre-rounded; A fragments cvt'd in-loop iff CVT_A.
// ---------------------------------------------------------------------------
template <bool CVT_A>
__device__ __forceinline__ void gemm_body_ldsm(
    const float* __restrict__ A, const float* __restrict__ WT,
    const float* __restrict__ bias, float* __restrict__ Cout,
    int ldout, int block_m, int wcol, int outcol, float* sm)
{
    const int K = 256;
    const int tid = threadIdx.x;
    const int wid = tid >> 5;          // 0..15
    const int lane = tid & 31;
    const int wm = (wid & 3) * 32;     // warp m offset
    const int wn = (wid >> 2) * 32;    // warp n offset
    const int lr = lane >> 2;
    const int lc = lane & 3;

    // staging: each thread 1 A cp16 + 1 B cp16
    const int arow = tid >> 2;          // 0..127 (m row / n row)
    const int acol = (tid & 3) * 4;     // k offset 0,4,8,12

    const float* Aptr = A + (size_t)(block_m + arow) * K + acol;
    const float* Wptr = WT + (size_t)(wcol + arow) * K + acol;

    // ldmatrix byte offsets (per-thread invariant)
    const int a_off = ((wm + (lane & 15)) * APITCH + ((lane >> 4) << 2)) * 4;
    const int b_row = wn + (lane & 7) + ((lane >> 4) << 3);
    const int b_off = (b_row * BPITCH + (((lane >> 3) & 1) << 2)) * 4;

    float acc[2][4][4];
#pragma unroll
    for (int i = 0; i < 2; i++)
#pragma unroll
        for (int j = 0; j < 4; j++)
#pragma unroll
            for (int t = 0; t < 4; t++) acc[i][j][t] = 0.f;

    const int NIT = K >> 4;   // 16

    auto issue_tile = [&](int s, int k0) {
        float* as = sm + s * STAGE_FLOATS;
        float* bs = as + A_TILE;
        cp16(smem_u32(as + arow * APITCH + acol), Aptr + k0);
        cp16(smem_u32(bs + arow * BPITCH + acol), Wptr + k0);
    };

#pragma unroll
    for (int s = 0; s < STAGES - 1; s++) {
        if (s < NIT) issue_tile(s, s * 16);
        asm volatile("cp.async.commit_group;");
    }

    for (int it = 0; it < NIT; it++) {
        asm volatile("cp.async.wait_group %0;" :: "n"(STAGES - 2));
        __syncthreads();
        if (it + STAGES - 1 < NIT)
            issue_tile((it + STAGES - 1) % STAGES, (it + STAGES - 1) * 16);
        asm volatile("cp.async.commit_group;");

        uint32_t sbase = smem_u32(sm + (it % STAGES) * STAGE_FLOATS);
        uint32_t ab = sbase;
        uint32_t bb = sbase + A_TILE * 4;
#pragma unroll
        for (int kk = 0; kk < 16; kk += 8) {
            uint32_t af0[4], af1[4], bf0[4], bf1[4];
            LDSM4(af0, ab + a_off + kk * 4);
            LDSM4(af1, ab + a_off + 16 * APITCH * 4 + kk * 4);
            LDSM4(bf0, bb + b_off + kk * 4);
            LDSM4(bf1, bb + b_off + 16 * BPITCH * 4 + kk * 4);
            if (CVT_A) {
#pragma unroll
                for (int i = 0; i < 4; i++) {
                    af0[i] = f2tf32(__uint_as_float(af0[i]));
                    af1[i] = f2tf32(__uint_as_float(af1[i]));
                }
            }
#pragma unroll
            for (int mf = 0; mf < 2; mf++) {
                const uint32_t* af = mf ? af1 : af0;
                mma_tf32(acc[mf][0], af, bf0[0], bf0[1]);
                mma_tf32(acc[mf][1], af, bf0[2], bf0[3]);
                mma_tf32(acc[mf][2], af, bf1[0], bf1[1]);
                mma_tf32(acc[mf][3], af, bf1[2], bf1[3]);
            }
        }
    }

#pragma unroll
    for (int mf = 0; mf < 2; mf++) {
        const int row0 = block_m + wm + mf * 16 + lr;
#pragma unroll
        for (int nf = 0; nf < 4; nf++) {
            const int cl = wn + nf * 8 + lc * 2;
            float2 bv = *(const float2*)(bias + wcol + cl);
            float2 v0 = make_float2(acc[mf][nf][0] + bv.x, acc[mf][nf][1] + bv.y);
            float2 v1 = make_float2(acc[mf][nf][2] + bv.x, acc[mf][nf][3] + bv.y);
            *(float2*)(Cout + (size_t)row0 * ldout + outcol + cl) = v0;
            *(float2*)(Cout + (size_t)(row0 + 8) * ldout + outcol + cl) = v1;
        }
    }
}

// Fused Q+KV projection: grid (6, 64), WT rows 0..767.
__global__ __launch_bounds__(512, 2) void qkv_gemm_kernel(
    const float* __restrict__ feat, float* __restrict__ qkv)
{
    extern __shared__ float sm[];
    gemm_body_ldsm<true>(feat, g_wt, g_bias768, qkv, 768,
                         blockIdx.y * 128, blockIdx.x * 128, blockIdx.x * 128, sm);
}

// Output projection: grid (2, 64). A pre-rounded -> no cvt.
__global__ __launch_bounds__(512, 2) void proj_gemm_kernel(
    const float* __restrict__ bias, float* __restrict__ out)
{
    extern __shared__ float sm[];
    gemm_body_ldsm<false>(g_attnout, g_wtp, bias, out, 256,
                          blockIdx.y * 128, blockIdx.x * 128, blockIdx.x * 128, sm);
}

// ---------------------------------------------------------------------------
// Fused gather + scores + softmax + weighted-V with active-member compaction.
// ---------------------------------------------------------------------------
__device__ __forceinline__ bool read_mask(const void* cm, int idx, int is_u8)
{
    if (is_u8) return ((const unsigned char*)cm)[idx] != 0;
    return ((const int*)cm)[idx] != 0;
}

__global__ __launch_bounds__(256) void attn_kernel(
    const int* __restrict__ member_idx,
    const void* __restrict__ cluster_mask,
    const int* __restrict__ pe_idx,
    const float* __restrict__ blank_k,
    const float* __restrict__ blank_v)
{
    extern __shared__ float smem[];
    float* kv    = smem;                 // 32 x KP (K only)
    float* qsh   = smem + 32 * KP;       // 256
    float* aw    = qsh + 256;            // 8 heads x 32 compacted weights
    int*   voffc = (int*)(aw + 256);     // 32 compacted V-row offsets

    const int bn   = blockIdx.x;
    const int tid  = threadIdx.x;
    const int h    = tid >> 5;
    const int lane = tid & 31;
    const int b    = bn >> 12;     // N = 4096
    const int is_u8 = g_mask_is_u8;

    // ---- phase 1: stage q + gathered K (cp.async), mask-predicated ----
    const int mbase = bn * Mm;
    const int mrow = tid >> 3;
    const int sub  = tid & 7;
    const bool msk_stage = read_mask(cluster_mask, mbase + mrow, is_u8);

    if (msk_stage) {
        const int gidx = __ldg(member_idx + mbase + mrow);
        const char* src = (const char*)(g_qkv + ((size_t)(b * Nn + gidx)) * 768 + 256);
        uint32_t dst_base = smem_u32(kv + mrow * KP);
#pragma unroll
        for (int j = 0; j < 8; j++) {
            cp16(dst_base + j * 128 + sub * 16, src + j * 256 + sub * 16);
        }
    }
    asm volatile("cp.async.commit_group;");

    qsh[tid] = g_qkv[(size_t)bn * 768 + tid];

    const bool msk = read_mask(cluster_mask, mbase + lane, is_u8);
    const unsigned wmask = __ballot_sync(0xFFFFFFFFu, msk);
    const int n_act = __popc(wmask);
    const int n4 = (n_act + 3) & ~3;
    const int pos = __popc(wmask & ((1u << lane) - 1u));

    if (tid < 32) {
        if (msk) {
            const int gidx_l = __ldg(member_idx + mbase + lane);
            voffc[pos] = gidx_l * 768;
        }
        if (lane >= n_act && lane < n4) voffc[lane] = 0;
    }

    asm volatile("cp.async.wait_group 0;");
    __syncthreads();

    // ---- phase 2: score + softmax (lane = member m) ----
    const float* qh = qsh + h * 32;
    float score = -3.0e38f;
    if (msk) {
        const float4* krow4 = (const float4*)(kv + lane * KP + h * 32);
        float sc = 0.f;
#pragma unroll
        for (int i = 0; i < 8; i++) {
            float4 kk = krow4[i];
            sc = fmaf(kk.x, qh[4*i+0], sc);
            sc = fmaf(kk.y, qh[4*i+1], sc);
            sc = fmaf(kk.z, qh[4*i+2], sc);
            sc = fmaf(kk.w, qh[4*i+3], sc);
        }
        const int pid = pe_idx[mbase + lane];
        score = sc * SCALE + g_pe[pid * Hh + h];
    }

    float bsp = qh[lane] * blank_k[h * 32 + lane];
#pragma unroll
    for (int o = 16; o > 0; o >>= 1)
        bsp += __shfl_xor_sync(0xFFFFFFFFu, bsp, o);
    const float bs = bsp * SCALE;

    float mx = score;
#pragma unroll
    for (int o = 16; o > 0; o >>= 1)
        mx = fmaxf(mx, __shfl_xor_sync(0xFFFFFFFFu, mx, o));
    mx = fmaxf(mx, bs);

    float p  = __expf(score - mx);
    float pb = __expf(bs - mx);
    float s = p;
#pragma unroll
    for (int o = 16; o > 0; o >>= 1)
        s += __shfl_xor_sync(0xFFFFFFFFu, s, o);
    s += pb;
    const float inv = 1.f / s;
    const float a  = p * inv;
    const float ab = pb * inv;

    if (msk) aw[h * 32 + pos] = a;
    if (lane >= n_act && lane < n4) aw[h * 32 + lane] = 0.f;
    __syncwarp();

    // ---- phase 3: dense weighted V sum over active members ----
    const float* vb = g_qkv + (size_t)b * Nn * 768 + 256 + h * 64 + 32 + lane;
    float out = ab * blank_v[h * 32 + lane];
    float out2 = 0.f;
    for (int c = 0; c < n4; c += 4) {
        int4   ro = *(const int4*)(voffc + c);
        float4 wv = *(const float4*)(aw + h * 32 + c);
        float v0 = __ldg(vb + ro.x);
        float v1 = __ldg(vb + ro.y);
        float v2 = __ldg(vb + ro.z);
        float v3 = __ldg(vb + ro.w);
        out  = fmaf(wv.x, v0, out);
        out2 = fmaf(wv.y, v1, out2);
        out  = fmaf(wv.z, v2, out);
        out2 = fmaf(wv.w, v3, out2);
    }
    out += out2;

    g_attnout[(size_t)bn * Cc + h * 32 + lane] = rna_tf32(out);
}

// ---------------------------------------------------------------------------
extern "C" void kernel_launch(void* const* d_in, const int* in_sizes, int n_in,
                              void* d_out, int out_size)
{
    const float* feat   = (const float*)d_in[0];
    const int*   member = (const int*)d_in[1];
    const void*  mask   = d_in[2];
    const int*   peidx  = (const int*)d_in[3];

    int p = 4;
    for (int i = 4; i < n_in; i++) {
        if (in_sizes[i] == 3125) { p = i; break; }
    }
    const float* pre_table = (const float*)d_in[p];
    const float* Wq        = (const float*)d_in[p + 1];
    const float* bq        = (const float*)d_in[p + 2];
    const float* Wkv       = (const float*)d_in[p + 3];
    const float* bkv       = (const float*)d_in[p + 4];
    const float* W_pe      = (const float*)d_in[p + 5];
    const float* b_pe      = (const float*)d_in[p + 6];
    const float* blank_k   = (const float*)d_in[p + 7];
    const float* blank_v   = (const float*)d_in[p + 8];
    const float* Wproj     = (const float*)d_in[p + 9];
    const float* bproj     = (const float*)d_in[p + 10];
    float* out = (float*)d_out;

    float* qkv = nullptr;
    cudaGetSymbolAddress((void**)&qkv, g_qkv);

    cudaFuncSetAttribute(attn_kernel,
                         cudaFuncAttributeMaxDynamicSharedMemorySize, ATTN_SMEM);
    cudaFuncSetAttribute(qkv_gemm_kernel,
                         cudaFuncAttributeMaxDynamicSharedMemorySize, GEMM_SMEM);
    cudaFuncSetAttribute(proj_gemm_kernel,
                         cudaFuncAttributeMaxDynamicSharedMemorySize, GEMM_SMEM);

    detect_mask_kernel<<<1, 256>>>((const unsigned int*)mask);
    pe_kernel<<<(T2 * Hh + 255) / 256, 256>>>(pre_table, W_pe, b_pe);
    {
        dim3 blk(32, 8);
        prep_w_kernel<<<257, blk>>>(Wq, Wkv, Wproj, bq, bkv);
    }

    {   // fused Q+KV projection
        dim3 grid(6, ROWS / 128);
        qkv_gemm_kernel<<<grid, 512, GEMM_SMEM>>>(feat, qkv);
    }

    attn_kernel<<<ROWS, 256, ATTN_SMEM>>>(member, mask, peidx, blank_k, blank_v);

    {   // output projection
        dim3 grid(2, ROWS / 128);
        proj_gemm_kernel<<<grid, 512, GEMM_SMEM>>>(bproj, out);
    }
}

// round 17
// speedup vs baseline: 1.0809x; 1.0191x over previous
#include <cuda_runtime.h>
#include <cuda_bf16.h>
#include <math.h>
#include <stdint.h>

// Problem constants
#define Bb 2
#define Nn 4096
#define Mm 32
#define Cc 256
#define Hh 8
#define T2 625
#define SCALE 0.17677669529663687f   // 32^-0.5
#define ROWS (Bb*Nn)                  // 8192

// attn smem
#define KP 260
#define ATTN_SMEM ((32*KP + 256 + 256 + 32) * 4) // 35456 bytes

// GEMM pipeline config (BM=BN=128, BK=16, pitch 20 both operands)
#define STAGES 4
#define APITCH 20
#define BPITCH 20
#define A_TILE (128*APITCH)
#define B_TILE (128*BPITCH)
#define STAGE_FLOATS (A_TILE + B_TILE)
#define GEMM_SMEM (STAGES*STAGE_FLOATS*4) // 81920 bytes

// Scratch
__device__ float g_qkv[(size_t)ROWS * 768];      // [q(256) | per-head (k32,v32) x8]
__device__ float g_attnout[(size_t)ROWS * Cc];   // tf32-rounded attention output
__device__ float g_wt[768 * 256];                // [n][k] rounded (Wq rows | Wkv rows)
__device__ float g_wtp[256 * 256];               // [n][k] Wproj rounded
__device__ float g_bias768[768];                 // [bq | bkv]
__device__ float g_pe[T2 * Hh];
__device__ int   g_mask_is_u8;

// ---------------------------------------------------------------------------
__device__ __forceinline__ uint32_t f2tf32(float f)
{
    uint32_t r;
    asm("cvt.rna.tf32.f32 %0, %1;" : "=r"(r) : "f"(f));
    return r;
}
__device__ __forceinline__ float rna_tf32(float f)
{
    return __uint_as_float(f2tf32(f));
}

__global__ void detect_mask_kernel(const unsigned int* __restrict__ m)
{
    int found = 0;
#pragma unroll
    for (int j = 0; j < 8; j++) {
        if (m[threadIdx.x + j * 256] > 1u) found = 1;
    }
    int any = __syncthreads_or(found);
    if (threadIdx.x == 0) g_mask_is_u8 = any;
}

__global__ void pe_kernel(const float* __restrict__ pre_table,
                          const float* __restrict__ W_pe,
                          const float* __restrict__ b_pe)
{
    int i = blockIdx.x * blockDim.x + threadIdx.x;
    if (i >= T2 * Hh) return;
    int t = i >> 3;
    int h = i & 7;
    float acc = b_pe[h];
#pragma unroll
    for (int j = 0; j < 5; j++)
        acc += pre_table[t * 5 + j] * W_pe[j * Hh + h];
    g_pe[i] = acc;
}

// ---------------------------------------------------------------------------
// prep: tiled transpose+round of weights into [n][k] layout; bias merge.
// ---------------------------------------------------------------------------
__global__ void prep_w_kernel(
    const float* __restrict__ Wq, const float* __restrict__ Wkv,
    const float* __restrict__ Wproj,
    const float* __restrict__ bq, const float* __restrict__ bkv)
{
    __shared__ float t[32][33];
    const int b = blockIdx.x;
    const int tx = threadIdx.x, ty = threadIdx.y;

    if (b == 256) {
        int tid = ty * 32 + tx;
#pragma unroll
        for (int j = 0; j < 3; j++) {
            int e = tid + j * 256;
            g_bias768[e] = (e < 256) ? bq[e] : bkv[e - 256];
        }
        return;
    }

    const float* src; float* dst;
    int N, kt, nt, row_off;
    if (b < 64)      { src = Wq;    N = 256; kt = b >> 3;        nt = b & 7;         dst = g_wt;  row_off = 0; }
    else if (b < 192){ int j = b - 64;  src = Wkv;  N = 512; kt = j >> 4; nt = j & 15; dst = g_wt;  row_off = 256; }
    else             { int j = b - 192; src = Wproj;N = 256; kt = j >> 3; nt = j & 7;  dst = g_wtp; row_off = 0; }

#pragma unroll
    for (int j = 0; j < 4; j++) {
        int k = kt * 32 + ty + j * 8;
        t[ty + j * 8][tx] = rna_tf32(src[(size_t)k * N + nt * 32 + tx]);
    }
    __syncthreads();
#pragma unroll
    for (int j = 0; j < 4; j++) {
        int n = nt * 32 + ty + j * 8;
        dst[(size_t)(row_off + n) * 256 + kt * 32 + tx] = t[tx][ty + j * 8];
    }
}

// ---------------------------------------------------------------------------
__device__ __forceinline__ void mma_tf32(float* d, const uint32_t* a,
                                         uint32_t b0, uint32_t b1)
{
    asm volatile(
        "mma.sync.aligned.m16n8k8.row.col.f32.tf32.tf32.f32 "
        "{%0,%1,%2,%3}, {%4,%5,%6,%7}, {%8,%9}, {%0,%1,%2,%3};"
        : "+f"(d[0]), "+f"(d[1]), "+f"(d[2]), "+f"(d[3])
        : "r"(a[0]), "r"(a[1]), "r"(a[2]), "r"(a[3]), "r"(b0), "r"(b1));
}

__device__ __forceinline__ uint32_t smem_u32(const void* p)
{
    uint32_t r;
    asm("{ .reg .u64 t; cvta.to.shared.u64 t, %1; cvt.u32.u64 %0, t; }"
        : "=r"(r) : "l"(p));
    return r;
}

__device__ __forceinline__ void cp16(uint32_t dst, const void* src)
{
    asm volatile("cp.async.ca.shared.global [%0], [%1], 16;"
                 :: "r"(dst), "l"(src));
}

#define LDSM4(r, addr) \
    asm volatile("ldmatrix.sync.aligned.m8n8.x4.shared.b16 {%0,%1,%2,%3}, [%4];" \
        : "=r"((r)[0]), "=r"((r)[1]), "=r"((r)[2]), "=r"((r)[3]) : "r"(addr))

// ---------------------------------------------------------------------------
// tf32 GEMM body, 512 threads, BM=BN=128, BK=16, 4-stage cp.async,
// ldmatrix fragment loads. A [m][k] row-major, WT [n][k] row-major (K=256).
// ---------------------------------------------------------------------------
template <bool CVT_A>
__device__ __forceinline__ void gemm_body_ldsm(
    const float* __restrict__ A, const float* __restrict__ WT,
    const float* __restrict__ bias, float* __restrict__ Cout,
    int ldout, int block_m, int wcol, int outcol, float* sm)
{
    const int K = 256;
    const int tid = threadIdx.x;
    const int wid = tid >> 5;
    const int lane = tid & 31;
    const int wm = (wid & 3) * 32;
    const int wn = (wid >> 2) * 32;
    const int lr = lane >> 2;
    const int lc = lane & 3;

    const int arow = tid >> 2;
    const int acol = (tid & 3) * 4;

    const float* Aptr = A + (size_t)(block_m + arow) * K + acol;
    const float* Wptr = WT + (size_t)(wcol + arow) * K + acol;

    const int a_off = ((wm + (lane & 15)) * APITCH + ((lane >> 4) << 2)) * 4;
    const int b_row = wn + (lane & 7) + ((lane >> 4) << 3);
    const int b_off = (b_row * BPITCH + (((lane >> 3) & 1) << 2)) * 4;

    float acc[2][4][4];
#pragma unroll
    for (int i = 0; i < 2; i++)
#pragma unroll
        for (int j = 0; j < 4; j++)
#pragma unroll
            for (int t = 0; t < 4; t++) acc[i][j][t] = 0.f;

    const int NIT = K >> 4;

    auto issue_tile = [&](int s, int k0) {
        float* as = sm + s * STAGE_FLOATS;
        float* bs = as + A_TILE;
        cp16(smem_u32(as + arow * APITCH + acol), Aptr + k0);
        cp16(smem_u32(bs + arow * BPITCH + acol), Wptr + k0);
    };

#pragma unroll
    for (int s = 0; s < STAGES - 1; s++) {
        if (s < NIT) issue_tile(s, s * 16);
        asm volatile("cp.async.commit_group;");
    }

    for (int it = 0; it < NIT; it++) {
        asm volatile("cp.async.wait_group %0;" :: "n"(STAGES - 2));
        __syncthreads();
        if (it + STAGES - 1 < NIT)
            issue_tile((it + STAGES - 1) % STAGES, (it + STAGES - 1) * 16);
        asm volatile("cp.async.commit_group;");

        uint32_t sbase = smem_u32(sm + (it % STAGES) * STAGE_FLOATS);
        uint32_t ab = sbase;
        uint32_t bb = sbase + A_TILE * 4;
#pragma unroll
        for (int kk = 0; kk < 16; kk += 8) {
            uint32_t af0[4], af1[4], bf0[4], bf1[4];
            LDSM4(af0, ab + a_off + kk * 4);
            LDSM4(af1, ab + a_off + 16 * APITCH * 4 + kk * 4);
            LDSM4(bf0, bb + b_off + kk * 4);
            LDSM4(bf1, bb + b_off + 16 * BPITCH * 4 + kk * 4);
            if (CVT_A) {
#pragma unroll
                for (int i = 0; i < 4; i++) {
                    af0[i] = f2tf32(__uint_as_float(af0[i]));
                    af1[i] = f2tf32(__uint_as_float(af1[i]));
                }
            }
#pragma unroll
            for (int mf = 0; mf < 2; mf++) {
                const uint32_t* af = mf ? af1 : af0;
                mma_tf32(acc[mf][0], af, bf0[0], bf0[1]);
                mma_tf32(acc[mf][1], af, bf0[2], bf0[3]);
                mma_tf32(acc[mf][2], af, bf1[0], bf1[1]);
                mma_tf32(acc[mf][3], af, bf1[2], bf1[3]);
            }
        }
    }

#pragma unroll
    for (int mf = 0; mf < 2; mf++) {
        const int row0 = block_m + wm + mf * 16 + lr;
#pragma unroll
        for (int nf = 0; nf < 4; nf++) {
            const int cl = wn + nf * 8 + lc * 2;
            float2 bv = *(const float2*)(bias + wcol + cl);
            float2 v0 = make_float2(acc[mf][nf][0] + bv.x, acc[mf][nf][1] + bv.y);
            float2 v1 = make_float2(acc[mf][nf][2] + bv.x, acc[mf][nf][3] + bv.y);
            *(float2*)(Cout + (size_t)row0 * ldout + outcol + cl) = v0;
            *(float2*)(Cout + (size_t)(row0 + 8) * ldout + outcol + cl) = v1;
        }
    }
}

// Fused Q+KV projection, row offset moff: grid (6, 32) per batch half.
__global__ __launch_bounds__(512, 2) void qkv_gemm_kernel(
    const float* __restrict__ feat, float* __restrict__ qkv, int moff)
{
    extern __shared__ float sm[];
    gemm_body_ldsm<true>(feat, g_wt, g_bias768, qkv, 768,
                         moff + blockIdx.y * 128, blockIdx.x * 128,
                         blockIdx.x * 128, sm);
}

// Output projection, row offset moff: grid (2, 32) per batch half.
__global__ __launch_bounds__(512, 2) void proj_gemm_kernel(
    const float* __restrict__ bias, float* __restrict__ out, int moff)
{
    extern __shared__ float sm[];
    gemm_body_ldsm<false>(g_attnout, g_wtp, bias, out, 256,
                          moff + blockIdx.y * 128, blockIdx.x * 128,
                          blockIdx.x * 128, sm);
}

// ---------------------------------------------------------------------------
// Fused gather + scores + softmax + weighted-V (block offset bn_off).
// ---------------------------------------------------------------------------
__device__ __forceinline__ bool read_mask(const void* cm, int idx, int is_u8)
{
    if (is_u8) return ((const unsigned char*)cm)[idx] != 0;
    return ((const int*)cm)[idx] != 0;
}

__global__ __launch_bounds__(256) void attn_kernel(
    const int* __restrict__ member_idx,
    const void* __restrict__ cluster_mask,
    const int* __restrict__ pe_idx,
    const float* __restrict__ blank_k,
    const float* __restrict__ blank_v,
    int bn_off)
{
    extern __shared__ float smem[];
    float* kv    = smem;                 // 32 x KP (K only)
    float* qsh   = smem + 32 * KP;       // 256
    float* aw    = qsh + 256;            // 8 heads x 32 compacted weights
    int*   voffc = (int*)(aw + 256);     // 32 compacted V-row offsets

    const int bn   = blockIdx.x + bn_off;
    const int tid  = threadIdx.x;
    const int h    = tid >> 5;
    const int lane = tid & 31;
    const int b    = bn >> 12;
    const int is_u8 = g_mask_is_u8;

    const int mbase = bn * Mm;
    const int mrow = tid >> 3;
    const int sub  = tid & 7;
    const bool msk_stage = read_mask(cluster_mask, mbase + mrow, is_u8);

    if (msk_stage) {
        const int gidx = __ldg(member_idx + mbase + mrow);
        const char* src = (const char*)(g_qkv + ((size_t)(b * Nn + gidx)) * 768 + 256);
        uint32_t dst_base = smem_u32(kv + mrow * KP);
#pragma unroll
        for (int j = 0; j < 8; j++) {
            cp16(dst_base + j * 128 + sub * 16, src + j * 256 + sub * 16);
        }
    }
    asm volatile("cp.async.commit_group;");

    qsh[tid] = g_qkv[(size_t)bn * 768 + tid];

    const bool msk = read_mask(cluster_mask, mbase + lane, is_u8);
    const unsigned wmask = __ballot_sync(0xFFFFFFFFu, msk);
    const int n_act = __popc(wmask);
    const int n4 = (n_act + 3) & ~3;
    const int pos = __popc(wmask & ((1u << lane) - 1u));

    if (tid < 32) {
        if (msk) {
            const int gidx_l = __ldg(member_idx + mbase + lane);
            voffc[pos] = gidx_l * 768;
        }
        if (lane >= n_act && lane < n4) voffc[lane] = 0;
    }

    asm volatile("cp.async.wait_group 0;");
    __syncthreads();

    const float* qh = qsh + h * 32;
    float score = -3.0e38f;
    if (msk) {
        const float4* krow4 = (const float4*)(kv + lane * KP + h * 32);
        float sc = 0.f;
#pragma unroll
        for (int i = 0; i < 8; i++) {
            float4 kk = krow4[i];
            sc = fmaf(kk.x, qh[4*i+0], sc);
            sc = fmaf(kk.y, qh[4*i+1], sc);
            sc = fmaf(kk.z, qh[4*i+2], sc);
            sc = fmaf(kk.w, qh[4*i+3], sc);
        }
        const int pid = pe_idx[mbase + lane];
        score = sc * SCALE + g_pe[pid * Hh + h];
    }

    float bsp = qh[lane] * blank_k[h * 32 + lane];
#pragma unroll
    for (int o = 16; o > 0; o >>= 1)
        bsp += __shfl_xor_sync(0xFFFFFFFFu, bsp, o);
    const float bs = bsp * SCALE;

    float mx = score;
#pragma unroll
    for (int o = 16; o > 0; o >>= 1)
        mx = fmaxf(mx, __shfl_xor_sync(0xFFFFFFFFu, mx, o));
    mx = fmaxf(mx, bs);

    float p  = __expf(score - mx);
    float pb = __expf(bs - mx);
    float s = p;
#pragma unroll
    for (int o = 16; o > 0; o >>= 1)
        s += __shfl_xor_sync(0xFFFFFFFFu, s, o);
    s += pb;
    const float inv = 1.f / s;
    const float a  = p * inv;
    const float ab = pb * inv;

    if (msk) aw[h * 32 + pos] = a;
    if (lane >= n_act && lane < n4) aw[h * 32 + lane] = 0.f;
    __syncwarp();

    const float* vb = g_qkv + (size_t)b * Nn * 768 + 256 + h * 64 + 32 + lane;
    float out = ab * blank_v[h * 32 + lane];
    float out2 = 0.f;
    for (int c = 0; c < n4; c += 4) {
        int4   ro = *(const int4*)(voffc + c);
        float4 wv = *(const float4*)(aw + h * 32 + c);
        float v0 = __ldg(vb + ro.x);
        float v1 = __ldg(vb + ro.y);
        float v2 = __ldg(vb + ro.z);
        float v3 = __ldg(vb + ro.w);
        out  = fmaf(wv.x, v0, out);
        out2 = fmaf(wv.y, v1, out2);
        out  = fmaf(wv.z, v2, out);
        out2 = fmaf(wv.w, v3, out2);
    }
    out += out2;

    g_attnout[(size_t)bn * Cc + h * 32 + lane] = rna_tf32(out);
}

// ---------------------------------------------------------------------------
extern "C" void kernel_launch(void* const* d_in, const int* in_sizes, int n_in,
                              void* d_out, int out_size)
{
    const float* feat   = (const float*)d_in[0];
    const int*   member = (const int*)d_in[1];
    const void*  mask   = d_in[2];
    const int*   peidx  = (const int*)d_in[3];

    int p = 4;
    for (int i = 4; i < n_in; i++) {
        if (in_sizes[i] == 3125) { p = i; break; }
    }
    const float* pre_table = (const float*)d_in[p];
    const float* Wq        = (const float*)d_in[p + 1];
    const float* bq        = (const float*)d_in[p + 2];
    const float* Wkv       = (const float*)d_in[p + 3];
    const float* bkv       = (const float*)d_in[p + 4];
    const float* W_pe      = (const float*)d_in[p + 5];
    const float* b_pe      = (const float*)d_in[p + 6];
    const float* blank_k   = (const float*)d_in[p + 7];
    const float* blank_v   = (const float*)d_in[p + 8];
    const float* Wproj     = (const float*)d_in[p + 9];
    const float* bproj     = (const float*)d_in[p + 10];
    float* out = (float*)d_out;

    float* qkv = nullptr;
    cudaGetSymbolAddress((void**)&qkv, g_qkv);

    cudaFuncSetAttribute(attn_kernel,
                         cudaFuncAttributeMaxDynamicSharedMemorySize, ATTN_SMEM);
    cudaFuncSetAttribute(qkv_gemm_kernel,
                         cudaFuncAttributeMaxDynamicSharedMemorySize, GEMM_SMEM);
    cudaFuncSetAttribute(proj_gemm_kernel,
                         cudaFuncAttributeMaxDynamicSharedMemorySize, GEMM_SMEM);

    // Side stream + fork/join events (capturable multi-stream pattern).
    cudaStream_t s1;
    cudaStreamCreateWithFlags(&s1, cudaStreamNonBlocking);
    cudaEvent_t ev_fork, ev_join;
    cudaEventCreateWithFlags(&ev_fork, cudaEventDisableTiming);
    cudaEventCreateWithFlags(&ev_join, cudaEventDisableTiming);

    // shared prologue on the capture (NULL) stream
    detect_mask_kernel<<<1, 256>>>((const unsigned int*)mask);
    pe_kernel<<<(T2 * Hh + 255) / 256, 256>>>(pre_table, W_pe, b_pe);
    {
        dim3 blk(32, 8);
        prep_w_kernel<<<257, blk>>>(Wq, Wkv, Wproj, bq, bkv);
    }

    cudaEventRecord(ev_fork, 0);
    cudaStreamWaitEvent(s1, ev_fork, 0);

    // chain 0 (batch 0) on NULL stream
    {
        dim3 grid(6, 32);
        qkv_gemm_kernel<<<grid, 512, GEMM_SMEM>>>(feat, qkv, 0);
    }
    attn_kernel<<<Nn, 256, ATTN_SMEM>>>(member, mask, peidx, blank_k, blank_v, 0);
    {
        dim3 grid(2, 32);
        proj_gemm_kernel<<<grid, 512, GEMM_SMEM>>>(bproj, out, 0);
    }

    // chain 1 (batch 1) on side stream
    {
        dim3 grid(6, 32);
        qkv_gemm_kernel<<<grid, 512, GEMM_SMEM, s1>>>(feat, qkv, 4096);
    }
    attn_kernel<<<Nn, 256, ATTN_SMEM, s1>>>(member, mask, peidx, blank_k, blank_v, 4096);
    {
        dim3 grid(2, 32);
        proj_gemm_kernel<<<grid, 512, GEMM_SMEM, s1>>>(bproj, out, 4096);
    }

    cudaEventRecord(ev_join, s1);
    cudaStreamWaitEvent(0, ev_join, 0);
}